// round 10
// baseline (speedup 1.0000x reference)
#include <cuda_runtime.h>

#define HH 200
#define WW 304
#define CC 256
#define NOUT 7
#define NSAMP 14          // NOUT * RATIO
#define NCORN 28          // 2 * NSAMP
#define WARPS 8
#define CH_PER_BLOCK 64   // CC / CSPLIT
#define CSPLIT 4

__global__ __launch_bounds__(256, 4)
void roi_align_kernel(const float* __restrict__ feat,
                      const float* __restrict__ boxes,
                      float* __restrict__ out)
{
    __shared__ int   s_cx[NCORN];
    __shared__ float s_fx[NSAMP];
    __shared__ int   s_vx[NSAMP];
    __shared__ int   s_cy[NCORN];
    __shared__ __align__(16) float s_wy[NCORN];   // 0.25 * y-weight * validity

    const int r   = blockIdx.x;
    const int tid = threadIdx.x;

    // ---- per-ROI bilinear metadata (threads 0..27) ----
    if (tid < 2 * NSAMP) {
        const int axis = tid / NSAMP;     // 0 = y, 1 = x
        const int i    = tid % NSAMP;
        const float b0 = boxes[r * 4 + (axis ? 0 : 1)] * 0.25f;  // x1 / y1
        const float b1 = boxes[r * 4 + (axis ? 2 : 3)] * 0.25f;  // x2 / y2
        const float len = fmaxf(b1 - b0, 1.0f);
        const float t   = b0 + (i + 0.5f) * 0.5f * (len / 7.0f);
        const int size  = axis ? WW : HH;
        const int valid = (t > -1.0f) && (t < (float)size);
        const float tc  = t < 0.0f ? 0.0f : t;
        const float low = floorf(tc);
        int lo, hi; float frac;
        if (low >= (float)(size - 1)) {
            lo = size - 1; hi = size - 1; frac = 0.0f;
        } else {
            lo = (int)low; hi = lo + 1; frac = tc - low;
        }
        if (axis) {
            s_cx[2 * i] = lo; s_cx[2 * i + 1] = hi; s_fx[i] = frac; s_vx[i] = valid;
        } else {
            // fold the 1/4 sample-average into the y weight (exact: power of 2)
            const float vm = valid ? 0.25f : 0.0f;
            s_cy[2 * i]     = lo;
            s_cy[2 * i + 1] = hi;
            s_wy[2 * i]     = (1.0f - frac) * vm;
            s_wy[2 * i + 1] = frac * vm;
        }
    }
    __syncthreads();

    const int warp = tid >> 5;
    const int lane = tid & 31;
    const int img  = r >> 9;                       // r / 512
    const float* fb = feat + (size_t)img * CC * HH * WW;
    const int c0 = blockIdx.y * CH_PER_BLOCK;

    // Per-lane x-corner column + separable x weight (frac * validity).
    // Lanes 28-31 mirror lane 27: same addresses (no extra lines), own inert
    // shuffle group, never writers.
    const int cidx = lane < NCORN ? lane : NCORN - 1;
    const int mycx = s_cx[cidx];
    float wx;
    {
        const int sx = cidx >> 1;
        const float fx = s_fx[sx];
        wx = ((cidx & 1) ? fx : 1.0f - fx) * (s_vx[sx] ? 1.0f : 0.0f);
    }

    // Per-lane absolute row offsets (plain int registers).
    int rowoff[NCORN];
    #pragma unroll
    for (int a = 0; a < NCORN; a++) rowoff[a] = s_cy[a] * WW + mycx;

    const int px = lane >> 2;                      // x-group id (valid for lane<28)
    const bool writer = (lane < NCORN) && ((lane & 3) == 0);

    for (int c = c0 + warp; c < c0 + CH_PER_BLOCK; c += WARPS) {
        const float* fc = fb + (size_t)c * (HH * WW);
        float* ob = out + ((size_t)r * CC + c) * (NOUT * NOUT);

        // gather + y-fold + x-weight + butterfly x-reduce, one row-group at a time
        #pragma unroll
        for (int q = 0; q < NOUT; q++) {
            const float4 w4 = *(const float4*)(s_wy + 4 * q);
            float acc;
            acc =      w4.x * __ldg(fc + rowoff[4 * q + 0]);
            acc = fmaf(w4.y,  __ldg(fc + rowoff[4 * q + 1]), acc);
            acc = fmaf(w4.z,  __ldg(fc + rowoff[4 * q + 2]), acc);
            acc = fmaf(w4.w,  __ldg(fc + rowoff[4 * q + 3]), acc);
            float v = acc * wx;
            v += __shfl_xor_sync(0xffffffffu, v, 1);
            v += __shfl_xor_sync(0xffffffffu, v, 2);
            if (writer) ob[q * NOUT + px] = v;
        }
    }
}

extern "C" void kernel_launch(void* const* d_in, const int* in_sizes, int n_in,
                              void* d_out, int out_size)
{
    const float* feat  = (const float*)d_in[0];   // (2,256,200,304) f32
    const float* boxes = (const float*)d_in[1];   // (2,512,4) f32
    float* out = (float*)d_out;                   // (1024,256,7,7) f32

    dim3 grid(1024, CSPLIT);
    dim3 block(256);
    roi_align_kernel<<<grid, block>>>(feat, boxes, out);
}